// round 1
// baseline (speedup 1.0000x reference)
#include <cuda_runtime.h>
#include <math.h>

#define BRAYS 4096
#define NSAMP 447
#define RLO 64
#define SHI 128
#define N3 (64*64*64)          // 262144
#define M3 (128*128*128)       // 2097152
#define VCH 19
#define STEPV 0.015625f        // STEP * VOXEL = 0.5 * 0.03125

// ---------------- scratch (device globals; no runtime allocation) -----------
__device__ float g_x1[64 * N3];          // conv1 output (relu/bn applied)
__device__ float g_x2[64 * N3];          // conv2 output
__device__ float g_vols[VCH * M3];       // density(1)+feature(15)+grad(3) @128^3
__device__ float g_sdfs[BRAYS * NSAMP];
__device__ float g_rgbs[BRAYS * NSAMP * 3];

// ---------------- conv1: 12 -> 64, 3x3x3, pad1, BN+ReLU ---------------------
__global__ void conv1_kernel(const float* __restrict__ gin,
                             const float* __restrict__ w,
                             const float* __restrict__ cb,
                             const float* __restrict__ bg,
                             const float* __restrict__ bb,
                             const float* __restrict__ bm,
                             const float* __restrict__ bv)
{
    __shared__ float ws[16 * 12 * 27];   // 20.7 KB
    __shared__ float sa[16], sc[16];
    const int tid = threadIdx.x;
    const int cob = blockIdx.y * 16;
    for (int i = tid; i < 16 * 12 * 27; i += 256) {
        int co = i / (12 * 27);
        ws[i] = w[(cob + co) * (12 * 27) + (i - co * (12 * 27))];
    }
    if (tid < 16) {
        int co = cob + tid;
        float s = bg[co] * rsqrtf(bv[co] + 1e-5f);
        sa[tid] = s;
        sc[tid] = cb[co] * s + bb[co] - bm[co] * s;
    }
    __syncthreads();
    int v = blockIdx.x * 256 + tid;
    if (v >= N3) return;
    int x = v & 63, y = (v >> 6) & 63, z = v >> 12;
    float acc[16];
#pragma unroll
    for (int i = 0; i < 16; i++) acc[i] = 0.f;
    for (int kz = 0; kz < 3; kz++) { int zz = z + kz - 1; if ((unsigned)zz >= 64u) continue;
    for (int ky = 0; ky < 3; ky++) { int yy = y + ky - 1; if ((unsigned)yy >= 64u) continue;
    for (int kx = 0; kx < 3; kx++) { int xx = x + kx - 1; if ((unsigned)xx >= 64u) continue;
        int base = (zz * 64 + yy) * 64 + xx;
        int koff = kz * 9 + ky * 3 + kx;
        for (int ci = 0; ci < 12; ci++) {
            float val = __ldg(&gin[ci * N3 + base]);
            const float* wp = &ws[ci * 27 + koff];
#pragma unroll
            for (int co = 0; co < 16; co++) acc[co] += val * wp[co * (12 * 27)];
        }
    }}}
#pragma unroll
    for (int co = 0; co < 16; co++)
        g_x1[(cob + co) * N3 + v] = fmaxf(acc[co] * sa[co] + sc[co], 0.f);
}

// ---------------- conv2: 76 -> 64, 3x3x3, pad1, BN+ReLU ---------------------
__global__ void conv2_kernel(const float* __restrict__ gin,
                             const float* __restrict__ w,
                             const float* __restrict__ cb,
                             const float* __restrict__ bg,
                             const float* __restrict__ bb,
                             const float* __restrict__ bm,
                             const float* __restrict__ bv)
{
    __shared__ float ws[16 * 19 * 27];   // 39 KB (one 19-ci chunk x 16 co)
    __shared__ float sa[16], sc[16];
    const int tid = threadIdx.x;
    const int cob = blockIdx.y * 16;
    if (tid < 16) {
        int co = cob + tid;
        float s = bg[co] * rsqrtf(bv[co] + 1e-5f);
        sa[tid] = s;
        sc[tid] = cb[co] * s + bb[co] - bm[co] * s;
    }
    int v = blockIdx.x * 256 + tid;
    bool act = v < N3;
    int x = v & 63, y = (v >> 6) & 63, z = v >> 12;
    float acc[16];
#pragma unroll
    for (int i = 0; i < 16; i++) acc[i] = 0.f;
    for (int ch = 0; ch < 4; ch++) {            // 4 chunks of 19 input channels
        __syncthreads();
        for (int i = tid; i < 16 * 19 * 27; i += 256) {
            int co = i / (19 * 27);
            int rest = i - co * (19 * 27);       // cil*27 + koff
            ws[i] = w[(cob + co) * (76 * 27) + ch * (19 * 27) + rest];
        }
        __syncthreads();
        if (act) {
            for (int kz = 0; kz < 3; kz++) { int zz = z + kz - 1; if ((unsigned)zz >= 64u) continue;
            for (int ky = 0; ky < 3; ky++) { int yy = y + ky - 1; if ((unsigned)yy >= 64u) continue;
            for (int kx = 0; kx < 3; kx++) { int xx = x + kx - 1; if ((unsigned)xx >= 64u) continue;
                int base = (zz * 64 + yy) * 64 + xx;
                int koff = kz * 9 + ky * 3 + kx;
                for (int cil = 0; cil < 19; cil++) {
                    int ci = ch * 19 + cil;
                    const float* ip = (ci < 12) ? (gin + ci * N3) : (g_x1 + (ci - 12) * N3);
                    float val = __ldg(&ip[base]);
                    const float* wp = &ws[cil * 27 + koff];
#pragma unroll
                    for (int co = 0; co < 16; co++) acc[co] += val * wp[co * (19 * 27)];
                }
            }}}
        }
    }
    if (!act) return;
#pragma unroll
    for (int co = 0; co < 16; co++)
        g_x2[(cob + co) * N3 + v] = fmaxf(acc[co] * sa[co] + sc[co], 0.f);
}

// ------- transposed conv: 140 -> 16, k3, stride-2 upsample 64^3 -> 128^3 ----
// out[co,o] = sum_{k valid} sum_ci in[ci, (o+k-1)/2] * c3_w[ci,co,2-kz,2-ky,2-kx]
__global__ void deconv_kernel(const float* __restrict__ gin,
                              const float* __restrict__ w,
                              const float* __restrict__ cb)
{
    __shared__ float ws[20 * 16 * 27];   // 34.6 KB, chunk of 20 input channels
    const int tid = threadIdx.x;
    int v = blockIdx.x * 256 + tid;
    bool act = v < M3;
    int ox = v & 127, oy = (v >> 7) & 127, oz = v >> 14;
    int kzl[2], izl[2], nz = 0;
    int kyl[2], iyl[2], ny = 0;
    int kxl[2], ixl[2], nx = 0;
#pragma unroll
    for (int k = 0; k < 3; k++) {
        int t = oz + k - 1;
        if (t >= 0 && !(t & 1) && (t >> 1) < 64) { kzl[nz] = k; izl[nz] = t >> 1; nz++; }
        t = oy + k - 1;
        if (t >= 0 && !(t & 1) && (t >> 1) < 64) { kyl[ny] = k; iyl[ny] = t >> 1; ny++; }
        t = ox + k - 1;
        if (t >= 0 && !(t & 1) && (t >> 1) < 64) { kxl[nx] = k; ixl[nx] = t >> 1; nx++; }
    }
    float acc[16];
#pragma unroll
    for (int i = 0; i < 16; i++) acc[i] = 0.f;
    for (int ch = 0; ch < 7; ch++) {            // 7 chunks of 20 input channels
        __syncthreads();
        for (int i = tid; i < 20 * 16 * 27; i += 256) {
            int cil = i / (16 * 27);
            int rem = i - cil * (16 * 27);
            int co = rem / 27;
            int k = rem - co * 27;
            int kz_ = k / 9, ky_ = (k / 3) % 3, kx_ = k % 3;
            int ci = ch * 20 + cil;
            // store flipped so kernel indexes with output-kernel coords directly
            ws[i] = w[ci * (16 * 27) + co * 27 + (2 - kz_) * 9 + (2 - ky_) * 3 + (2 - kx_)];
        }
        __syncthreads();
        if (act) {
            for (int a = 0; a < nz; a++)
            for (int b = 0; b < ny; b++)
            for (int c = 0; c < nx; c++) {
                int base = (izl[a] * 64 + iyl[b]) * 64 + ixl[c];
                int koff = kzl[a] * 9 + kyl[b] * 3 + kxl[c];
                for (int cil = 0; cil < 20; cil++) {
                    int ci = ch * 20 + cil;
                    const float* ip = (ci < 12) ? (gin + ci * N3)
                                    : (ci < 76) ? (g_x1 + (ci - 12) * N3)
                                                : (g_x2 + (ci - 76) * N3);
                    float val = __ldg(&ip[base]);
                    const float* wp = &ws[cil * (16 * 27) + koff];
#pragma unroll
                    for (int co = 0; co < 16; co++) acc[co] += val * wp[co * 27];
                }
            }
        }
    }
    if (!act) return;
#pragma unroll
    for (int co = 0; co < 16; co++)
        g_vols[co * M3 + v] = acc[co] + __ldg(&cb[co]);
}

// ---------------- sobel: density -> 3 gradient channels, 5x5x5 pad2 ---------
__global__ void sobel_kernel(const float* __restrict__ sob)
{
    __shared__ float ks[3 * 125];
    const int tid = threadIdx.x;
    for (int i = tid; i < 375; i += 256) ks[i] = sob[i];
    __syncthreads();
    int v = blockIdx.x * 256 + tid;
    if (v >= M3) return;
    int x = v & 127, y = (v >> 7) & 127, z = v >> 14;
    float a0 = 0.f, a1 = 0.f, a2 = 0.f;
    for (int kz = 0; kz < 5; kz++) { int zz = z + kz - 2; if ((unsigned)zz >= 128u) continue;
    for (int ky = 0; ky < 5; ky++) { int yy = y + ky - 2; if ((unsigned)yy >= 128u) continue;
    for (int kx = 0; kx < 5; kx++) { int xx = x + kx - 2; if ((unsigned)xx >= 128u) continue;
        float val = g_vols[(zz * 128 + yy) * 128 + xx];
        int k = kz * 25 + ky * 5 + kx;
        a0 += val * ks[k];
        a1 += val * ks[125 + k];
        a2 += val * ks[250 + k];
    }}}
    g_vols[16 * M3 + v] = a0;
    g_vols[17 * M3 + v] = a1;
    g_vols[18 * M3 + v] = a2;
}

// ------------- per-sample: ray AABB, trilinear gather, MLP -------------------
__global__ void __launch_bounds__(128)
sample_kernel(const float* __restrict__ rays_o, const float* __restrict__ rays_d,
              const float* __restrict__ viewdirs,
              const float* __restrict__ w0, const float* __restrict__ b0,
              const float* __restrict__ w1, const float* __restrict__ b1,
              const float* __restrict__ w2, const float* __restrict__ b2,
              const float* __restrict__ w3, const float* __restrict__ b3,
              float* __restrict__ out)
{
    __shared__ float s_w0[58 * 64];
    __shared__ float s_w1[64 * 64];
    __shared__ float s_w2[64 * 64];
    __shared__ float s_w3[64 * 3];
    const int tid = threadIdx.x;
    for (int i = tid; i < 58 * 64; i += 128) s_w0[i] = w0[i];
    for (int i = tid; i < 64 * 64; i += 128) { s_w1[i] = w1[i]; s_w2[i] = w2[i]; }
    for (int i = tid; i < 192; i += 128) s_w3[i] = w3[i];
    __syncthreads();

    int idx = blockIdx.x * 128 + tid;
    if (idx >= BRAYS * NSAMP) return;
    int ray = idx / NSAMP;
    int s   = idx - ray * NSAMP;

    float ox = rays_o[ray * 3 + 0], oy = rays_o[ray * 3 + 1], oz = rays_o[ray * 3 + 2];
    float dx = rays_d[ray * 3 + 0], dy = rays_d[ray * 3 + 1], dz = rays_d[ray * 3 + 2];
    float vx = (dx == 0.f) ? 1e-6f : dx;
    float vy = (dy == 0.f) ? 1e-6f : dy;
    float vz = (dz == 0.f) ? 1e-6f : dz;
    float rax = (1.f - ox) / vx, rbx = (-1.f - ox) / vx;
    float ray_ = (1.f - oy) / vy, rby = (-1.f - oy) / vy;
    float raz = (1.f - oz) / vz, rbz = (-1.f - oz) / vz;
    float tmn = fmaxf(fmaxf(fminf(rax, rbx), fminf(ray_, rby)), fminf(raz, rbz));
    float tmx = fminf(fminf(fmaxf(rax, rbx), fmaxf(ray_, rby)), fmaxf(raz, rbz));
    float t_min = fminf(fmaxf(tmn, 0.05f), 2.5f);
    float t_max = fminf(fmaxf(tmx, 0.05f), 2.5f);
    bool mask = (t_max <= t_min);
    float dn = sqrtf(dx * dx + dy * dy + dz * dz);
    float interpx = t_min + STEPV * (float)s / dn;
    float px = ox + dx * interpx, py = oy + dy * interpx, pz = oz + dz * interpx;
    mask = mask || (px < -1.f) || (px > 1.f) || (py < -1.f) || (py > 1.f)
                || (pz < -1.f) || (pz > 1.f);
    if (mask) {
        g_sdfs[idx] = 100.f;
        g_rgbs[idx * 3 + 0] = 0.f;
        g_rgbs[idx * 3 + 1] = 0.f;
        g_rgbs[idx * 3 + 2] = 0.f;
        if (s == NSAMP - 1) out[BRAYS * 5 + ray] = 0.f;   // angle_n_d (masked -> 0)
        return;
    }
    // trilinear gather from 19-channel 128^3 volume
    float fx = fminf(fmaxf((px + 1.f) * 63.5f, 0.f), 127.f);
    float fy = fminf(fmaxf((py + 1.f) * 63.5f, 0.f), 127.f);
    float fz = fminf(fmaxf((pz + 1.f) * 63.5f, 0.f), 127.f);
    int i0x = (int)floorf(fx), i0y = (int)floorf(fy), i0z = (int)floorf(fz);
    int i1x = min(i0x + 1, 127), i1y = min(i0y + 1, 127), i1z = min(i0z + 1, 127);
    float twx = fx - (float)i0x, twy = fy - (float)i0y, twz = fz - (float)i0z;
    float wx0 = 1.f - twx, wy0 = 1.f - twy, wz0 = 1.f - twz;
    int o00 = (i0x * 128 + i0y) * 128;
    int o01 = (i0x * 128 + i1y) * 128;
    int o10 = (i1x * 128 + i0y) * 128;
    int o11 = (i1x * 128 + i1y) * 128;
    float w000 = wx0 * wy0 * wz0, w001 = wx0 * wy0 * twz;
    float w010 = wx0 * twy * wz0, w011 = wx0 * twy * twz;
    float w100 = twx * wy0 * wz0, w101 = twx * wy0 * twz;
    float w110 = twx * twy * wz0, w111 = twx * twy * twz;
    float samp[19];
#pragma unroll
    for (int c = 0; c < 19; c++) {
        const float* vc = g_vols + c * M3;
        samp[c] = w000 * __ldg(&vc[o00 + i0z]) + w001 * __ldg(&vc[o00 + i1z])
                + w010 * __ldg(&vc[o01 + i0z]) + w011 * __ldg(&vc[o01 + i1z])
                + w100 * __ldg(&vc[o10 + i0z]) + w101 * __ldg(&vc[o10 + i1z])
                + w110 * __ldg(&vc[o11 + i0z]) + w111 * __ldg(&vc[o11 + i1z]);
    }
    g_sdfs[idx] = samp[0];
    float gx = samp[16], gy = samp[17], gz = samp[18];
    float gn = sqrtf(gx * gx + gy * gy + gz * gz);
    float inv = 1.f / fmaxf(gn, 1e-12f);
    float nxx = gx * inv, nyy = gy * inv, nzz = gz * inv;
    float ux = viewdirs[ray * 3 + 0], uy = viewdirs[ray * 3 + 1], uz = viewdirs[ray * 3 + 2];
    float dot = -(ux * nxx + uy * nyy + uz * nzz);
    if (s == NSAMP - 1) out[BRAYS * 5 + ray] = -dot;      // n . v
    float rx = 2.f * dot * nxx + ux;
    float ry = 2.f * dot * nyy + uy;
    float rz = 2.f * dot * nzz + uz;

    float h[58];
#pragma unroll
    for (int c = 0; c < 15; c++) h[c] = samp[1 + c];
    h[15] = dot;
    h[16] = rx; h[17] = ry; h[18] = rz;
    {
        int p = 19;
        float fr = 1.f;
#pragma unroll
        for (int e = 0; e < 6; e++) {
            h[p++] = sinf(rx * fr); h[p++] = sinf(ry * fr); h[p++] = sinf(rz * fr);
            h[p++] = cosf(rx * fr); h[p++] = cosf(ry * fr); h[p++] = cosf(rz * fr);
            fr *= 2.f;
        }
    }
    h[55] = px; h[56] = py; h[57] = pz;

    float a0[64], a1[64];
#pragma unroll
    for (int j = 0; j < 64; j++) a0[j] = __ldg(&b0[j]);
    for (int i = 0; i < 58; i++) {
        float hv = h[i];
        const float4* wp = reinterpret_cast<const float4*>(s_w0 + i * 64);
#pragma unroll
        for (int j = 0; j < 16; j++) {
            float4 w4 = wp[j];
            a0[4 * j + 0] += hv * w4.x;
            a0[4 * j + 1] += hv * w4.y;
            a0[4 * j + 2] += hv * w4.z;
            a0[4 * j + 3] += hv * w4.w;
        }
    }
#pragma unroll
    for (int j = 0; j < 64; j++) { a0[j] = fmaxf(a0[j], 0.f); a1[j] = __ldg(&b1[j]); }
    for (int i = 0; i < 64; i++) {
        float hv = a0[i];
        const float4* wp = reinterpret_cast<const float4*>(s_w1 + i * 64);
#pragma unroll
        for (int j = 0; j < 16; j++) {
            float4 w4 = wp[j];
            a1[4 * j + 0] += hv * w4.x;
            a1[4 * j + 1] += hv * w4.y;
            a1[4 * j + 2] += hv * w4.z;
            a1[4 * j + 3] += hv * w4.w;
        }
    }
#pragma unroll
    for (int j = 0; j < 64; j++) { a1[j] = fmaxf(a1[j], 0.f); a0[j] = __ldg(&b2[j]); }
    for (int i = 0; i < 64; i++) {
        float hv = a1[i];
        const float4* wp = reinterpret_cast<const float4*>(s_w2 + i * 64);
#pragma unroll
        for (int j = 0; j < 16; j++) {
            float4 w4 = wp[j];
            a0[4 * j + 0] += hv * w4.x;
            a0[4 * j + 1] += hv * w4.y;
            a0[4 * j + 2] += hv * w4.z;
            a0[4 * j + 3] += hv * w4.w;
        }
    }
    float r0 = __ldg(&b3[0]), r1 = __ldg(&b3[1]), r2 = __ldg(&b3[2]);
    for (int i = 0; i < 64; i++) {
        float hv = fmaxf(a0[i], 0.f);
        r0 += hv * s_w3[i * 3 + 0];
        r1 += hv * s_w3[i * 3 + 1];
        r2 += hv * s_w3[i * 3 + 2];
    }
    g_rgbs[idx * 3 + 0] = r0;
    g_rgbs[idx * 3 + 1] = r1;
    g_rgbs[idx * 3 + 2] = r2;
}

// ---------------- per-ray compositing ----------------------------------------
__global__ void render_kernel(const float* __restrict__ rays_o,
                              const float* __restrict__ rays_d,
                              const float* __restrict__ variance,
                              float* __restrict__ out)
{
    int ray = blockIdx.x * blockDim.x + threadIdx.x;
    if (ray >= BRAYS) return;
    float scale = expf(variance[0] * 10.f);
    float ox = rays_o[ray * 3 + 0], oy = rays_o[ray * 3 + 1], oz = rays_o[ray * 3 + 2];
    float dx = rays_d[ray * 3 + 0], dy = rays_d[ray * 3 + 1], dz = rays_d[ray * 3 + 2];
    float vx = (dx == 0.f) ? 1e-6f : dx;
    float vy = (dy == 0.f) ? 1e-6f : dy;
    float vz = (dz == 0.f) ? 1e-6f : dz;
    float rax = (1.f - ox) / vx, rbx = (-1.f - ox) / vx;
    float ray_ = (1.f - oy) / vy, rby = (-1.f - oy) / vy;
    float raz = (1.f - oz) / vz, rbz = (-1.f - oz) / vz;
    float tmn = fmaxf(fmaxf(fminf(rax, rbx), fminf(ray_, rby)), fminf(raz, rbz));
    float t_min = fminf(fmaxf(tmn, 0.05f), 2.5f);
    float dn = sqrtf(dx * dx + dy * dy + dz * dz);
    float base_dist = t_min * dn;

    float T = 1.f, rgb0 = 0.f, rgb1 = 0.f, rgb2 = 0.f, depth = 0.f;
    float sd_prev = 1.f / (1.f + expf(-g_sdfs[ray * NSAMP] * scale));
    for (int s = 0; s < NSAMP - 1; s++) {
        float sd_next = 1.f / (1.f + expf(-g_sdfs[ray * NSAMP + s + 1] * scale));
        float alpha = fmaxf((sd_prev - sd_next) / (sd_prev + 1e-10f), 0.f);
        float wgt = T * alpha;
        T *= (1.f - alpha);
        out[BRAYS * 6 + ray * (NSAMP - 1) + s] = wgt;
        rgb0 += wgt * g_rgbs[(ray * NSAMP + s) * 3 + 0];
        rgb1 += wgt * g_rgbs[(ray * NSAMP + s) * 3 + 1];
        rgb2 += wgt * g_rgbs[(ray * NSAMP + s) * 3 + 2];
        depth += wgt * (base_dist + STEPV * (float)s);
        sd_prev = sd_next;
    }
    out[ray * 3 + 0] = rgb0;
    out[ray * 3 + 1] = rgb1;
    out[ray * 3 + 2] = rgb2;
    out[BRAYS * 3 + ray] = depth;
    out[BRAYS * 4 + ray] = T;    // bg = T[..., -1]
}

// -----------------------------------------------------------------------------
extern "C" void kernel_launch(void* const* d_in, const int* in_sizes, int n_in,
                              void* d_out, int out_size)
{
    const float* rays_o   = (const float*)d_in[0];
    const float* rays_d   = (const float*)d_in[1];
    const float* viewdirs = (const float*)d_in[2];
    const float* grid     = (const float*)d_in[3];
    const float* c1_w     = (const float*)d_in[4];
    const float* c1_b     = (const float*)d_in[5];
    const float* bn1_g    = (const float*)d_in[6];
    const float* bn1_beta = (const float*)d_in[7];
    const float* bn1_m    = (const float*)d_in[8];
    const float* bn1_v    = (const float*)d_in[9];
    const float* c2_w     = (const float*)d_in[10];
    const float* c2_b     = (const float*)d_in[11];
    const float* bn2_g    = (const float*)d_in[12];
    const float* bn2_beta = (const float*)d_in[13];
    const float* bn2_m    = (const float*)d_in[14];
    const float* bn2_v    = (const float*)d_in[15];
    const float* c3_w     = (const float*)d_in[16];
    const float* c3_b     = (const float*)d_in[17];
    const float* sobel    = (const float*)d_in[18];
    const float* variance = (const float*)d_in[19];
    const float* w0       = (const float*)d_in[20];
    const float* b0       = (const float*)d_in[21];
    const float* w1       = (const float*)d_in[22];
    const float* b1       = (const float*)d_in[23];
    const float* w2       = (const float*)d_in[24];
    const float* b2       = (const float*)d_in[25];
    const float* w3       = (const float*)d_in[26];
    const float* b3       = (const float*)d_in[27];
    float* out = (float*)d_out;

    dim3 cgrid((N3 + 255) / 256, 4);
    conv1_kernel<<<cgrid, 256>>>(grid, c1_w, c1_b, bn1_g, bn1_beta, bn1_m, bn1_v);
    conv2_kernel<<<cgrid, 256>>>(grid, c2_w, c2_b, bn2_g, bn2_beta, bn2_m, bn2_v);
    deconv_kernel<<<(M3 + 255) / 256, 256>>>(grid, c3_w, c3_b);
    sobel_kernel<<<(M3 + 255) / 256, 256>>>(sobel);
    int total = BRAYS * NSAMP;
    sample_kernel<<<(total + 127) / 128, 128>>>(rays_o, rays_d, viewdirs,
                                                w0, b0, w1, b1, w2, b2, w3, b3, out);
    render_kernel<<<(BRAYS + 127) / 128, 128>>>(rays_o, rays_d, variance, out);
}

// round 2
// speedup vs baseline: 1.8432x; 1.8432x over previous
#include <cuda_runtime.h>
#include <math.h>

#define BRAYS 4096
#define NSAMP 447
#define N3 (64*64*64)          // 262144
#define M3 (128*128*128)       // 2097152
#define VCH 19
#define STEPV 0.015625f        // STEP * VOXEL

// ---------------- scratch (device globals; no runtime allocation) -----------
__device__ float g_x1[64 * N3];
__device__ float g_x2[64 * N3];
__device__ float g_vols[VCH * M3];
__device__ float g_sdfs[BRAYS * NSAMP];
__device__ float g_rgbs[BRAYS * NSAMP * 3];

// =================== tiled 3x3x3 conv + BN + ReLU ===========================
// out tile 8(x) x 8(y) x 4(z), 64 output channels. 256 threads:
// tid = cg(8 co-groups of 8) + 8*row(32 rows: ry 8 x rz 4). Thread owns
// 8 x-consecutive voxels x 8 output channels = 64 register accumulators.
template<int CIN, int NCH, int LAYER>
__global__ void __launch_bounds__(256) conv3x3_kernel(
    const float* __restrict__ src0,      // grid (12 ch); ci>=12 comes from g_x1
    const float* __restrict__ w,
    const float* __restrict__ cb,
    const float* __restrict__ bg, const float* __restrict__ bb,
    const float* __restrict__ bm, const float* __restrict__ bv)
{
    __shared__ float s_in[4 * 6 * 10 * 12];   // [cil][z6][y10][x12]
    __shared__ float s_w[4 * 27 * 64];        // [cil][k27][co64]
    __shared__ float s_a[64], s_c[64];
    float* dst = (LAYER == 1) ? g_x1 : g_x2;

    const int tid = threadIdx.x;
    const int x0 = blockIdx.x * 8, y0 = blockIdx.y * 8, z0 = blockIdx.z * 4;
    if (tid < 64) {
        float s = bg[tid] * rsqrtf(bv[tid] + 1e-5f);
        s_a[tid] = s;
        s_c[tid] = cb[tid] * s + bb[tid] - bm[tid] * s;
    }
    const int cg = tid & 7;
    const int rowid = tid >> 3;
    const int ry = rowid & 7, rz = rowid >> 3;

    float acc[8][8];   // [x][c]
#pragma unroll
    for (int x = 0; x < 8; x++)
#pragma unroll
        for (int c = 0; c < 8; c++) acc[x][c] = 0.f;

    for (int ch = 0; ch < NCH; ch++) {
        __syncthreads();
        // stage input tile (zero-padded at volume borders)
        for (int i = tid; i < 4 * 720; i += 256) {
            int cil = i / 720, rem = i % 720;
            int z = rem / 120, y2 = (rem / 12) % 10, x = rem % 12;
            float vv = 0.f;
            int gx = x0 - 1 + x, gy = y0 - 1 + y2, gz = z0 - 1 + z;
            if (x < 10 && (unsigned)gx < 64u && (unsigned)gy < 64u && (unsigned)gz < 64u) {
                int ci = ch * 4 + cil;
                const float* sp = (ci < 12) ? (src0 + ci * N3) : (g_x1 + (ci - 12) * N3);
                vv = __ldg(&sp[(gz * 64 + gy) * 64 + gx]);
            }
            s_in[i] = vv;
        }
        // stage weights [cil][k][co]
        for (int i = tid; i < 4 * 27 * 64; i += 256) {
            int co = i & 63, rest = i >> 6;
            int k = rest % 27, cil = rest / 27;
            s_w[i] = __ldg(&w[co * (CIN * 27) + (ch * 4 + cil) * 27 + k]);
        }
        __syncthreads();
#pragma unroll
        for (int cil = 0; cil < 4; cil++) {
            const float* inc = s_in + cil * 720;
            const float* wc  = s_w + cil * 27 * 64;
#pragma unroll
            for (int kz = 0; kz < 3; kz++)
#pragma unroll
            for (int ky = 0; ky < 3; ky++) {
                const float4* rp = (const float4*)(inc + ((rz + kz) * 10 + ry + ky) * 12);
                float4 ra = rp[0], rb = rp[1], rc = rp[2];
                float rr[12] = {ra.x, ra.y, ra.z, ra.w, rb.x, rb.y, rb.z, rb.w,
                                rc.x, rc.y, rc.z, rc.w};
#pragma unroll
                for (int kx = 0; kx < 3; kx++) {
                    const float4* wp = (const float4*)(wc + (kz * 9 + ky * 3 + kx) * 64 + cg * 8);
                    float4 wA = wp[0], wB = wp[1];
                    float wv[8] = {wA.x, wA.y, wA.z, wA.w, wB.x, wB.y, wB.z, wB.w};
#pragma unroll
                    for (int x = 0; x < 8; x++)
#pragma unroll
                        for (int c = 0; c < 8; c++)
                            acc[x][c] += rr[kx + x] * wv[c];
                }
            }
        }
    }
    // write out with BN + ReLU
    int vbase = ((z0 + rz) * 64 + (y0 + ry)) * 64 + x0;
#pragma unroll
    for (int c = 0; c < 8; c++) {
        int co = cg * 8 + c;
        float a = s_a[co], cc = s_c[co];
        float* dp = dst + co * N3 + vbase;
#pragma unroll
        for (int x = 0; x < 8; x++)
            dp[x] = fmaxf(acc[x][c] * a + cc, 0.f);
    }
}

// ========= tiled transposed conv: 140 -> 16, k3, stride 2, 64^3 -> 128^3 ====
// out tile 16(x) x 8(y) x 8(z), 16 co. 256 threads: qx(4) x ty(8) x tz(8).
// Thread owns 4 x-consecutive outputs x 16 co.
__global__ void __launch_bounds__(256) deconv_kernel(
    const float* __restrict__ src0,   // grid
    const float* __restrict__ w,
    const float* __restrict__ cb)
{
    __shared__ float s_in[4 * 5 * 5 * 10];  // [cil][z5][y5][x10]
    __shared__ float s_w[4 * 27 * 16];      // [cil][kz][ky][kx][co16], flipped

    const int tid = threadIdx.x;
    const int x0 = blockIdx.x * 16, y0 = blockIdx.y * 8, z0 = blockIdx.z * 8;
    const int qx = tid & 3, ty = (tid >> 2) & 7, tz = tid >> 5;
    const int oy = y0 + ty, oz = z0 + tz;

    int nzl, kzv[2], izv[2];
    if ((tz & 1) == 0) { nzl = 1; kzv[0] = 1; izv[0] = tz >> 1; kzv[1] = 1; izv[1] = tz >> 1; }
    else { nzl = 2; kzv[0] = 0; izv[0] = (tz - 1) >> 1; kzv[1] = 2; izv[1] = (tz + 1) >> 1; }
    int nyl, kyv[2], iyv[2];
    if ((ty & 1) == 0) { nyl = 1; kyv[0] = 1; iyv[0] = ty >> 1; kyv[1] = 1; iyv[1] = ty >> 1; }
    else { nyl = 2; kyv[0] = 0; iyv[0] = (ty - 1) >> 1; kyv[1] = 2; iyv[1] = (ty + 1) >> 1; }

    float acc[4][16];
#pragma unroll
    for (int j = 0; j < 4; j++)
#pragma unroll
        for (int c = 0; c < 16; c++) acc[j][c] = 0.f;

    const int bx2 = x0 >> 1, by2 = y0 >> 1, bz2 = z0 >> 1;

    for (int ch = 0; ch < 35; ch++) {
        __syncthreads();
        // stage input tile (zero fill past volume edge)
        for (int i = tid; i < 4 * 250; i += 256) {
            int cil = i / 250, rem = i % 250;
            int z = rem / 50, y2 = (rem / 10) % 5, x = rem % 10;
            float vv = 0.f;
            int gx = bx2 + x, gy = by2 + y2, gz = bz2 + z;
            if (gx < 64 && gy < 64 && gz < 64) {
                int ci = ch * 4 + cil;
                const float* sp = (ci < 12) ? (src0 + ci * N3)
                                : (ci < 76) ? (g_x1 + (ci - 12) * N3)
                                            : (g_x2 + (ci - 76) * N3);
                vv = __ldg(&sp[(gz * 64 + gy) * 64 + gx]);
            }
            s_in[i] = vv;
        }
        // stage flipped weights [cil][kz][ky][kx][co]
        for (int i = tid; i < 4 * 27 * 16; i += 256) {
            int co = i & 15, rest = i >> 4;
            int k = rest % 27, cil = rest / 27;
            int kz_ = k / 9, ky_ = (k / 3) % 3, kx_ = k % 3;
            s_w[i] = __ldg(&w[(ch * 4 + cil) * (16 * 27) + co * 27
                              + (2 - kz_) * 9 + (2 - ky_) * 3 + (2 - kx_)]);
        }
        __syncthreads();
#pragma unroll
        for (int cil = 0; cil < 4; cil++) {
            for (int a = 0; a < nzl; a++) {
                int kz = kzv[a], iz = izv[a];
                for (int b = 0; b < nyl; b++) {
                    int ky = kyv[b], iy = iyv[b];
                    const float* rowp = s_in + ((cil * 5 + iz) * 5 + iy) * 10 + 2 * qx;
                    float2 rA = *(const float2*)rowp;
                    float  r2v = rowp[2];
                    float r0 = rA.x, r1 = rA.y;
                    const float* wb = s_w + ((cil * 27) + kz * 9 + ky * 3) * 16;
                    float w0v[16], w1v[16], w2v[16];
#pragma unroll
                    for (int q = 0; q < 4; q++) {
                        float4 t0 = ((const float4*)(wb))[q];
                        float4 t1 = ((const float4*)(wb + 16))[q];
                        float4 t2 = ((const float4*)(wb + 32))[q];
                        w0v[4*q+0]=t0.x; w0v[4*q+1]=t0.y; w0v[4*q+2]=t0.z; w0v[4*q+3]=t0.w;
                        w1v[4*q+0]=t1.x; w1v[4*q+1]=t1.y; w1v[4*q+2]=t1.z; w1v[4*q+3]=t1.w;
                        w2v[4*q+0]=t2.x; w2v[4*q+1]=t2.y; w2v[4*q+2]=t2.z; w2v[4*q+3]=t2.w;
                    }
#pragma unroll
                    for (int c = 0; c < 16; c++) {
                        acc[0][c] += r0 * w1v[c];                       // ox even: kx=1
                        acc[1][c] += r0 * w0v[c];                       // ox odd: kx=0
                        acc[1][c] += r1 * w2v[c];                       //         kx=2
                        acc[2][c] += r1 * w1v[c];
                        acc[3][c] += r1 * w0v[c];
                        acc[3][c] += r2v * w2v[c];
                    }
                }
            }
        }
    }
    int obase = (oz * 128 + oy) * 128 + x0 + 4 * qx;
#pragma unroll
    for (int c = 0; c < 16; c++) {
        float bias = __ldg(&cb[c]);
        float4 o4 = make_float4(acc[0][c] + bias, acc[1][c] + bias,
                                acc[2][c] + bias, acc[3][c] + bias);
        *(float4*)(g_vols + c * M3 + obase) = o4;
    }
}

// ---------------- sobel: density -> 3 gradient channels, 5x5x5 pad2 ---------
__global__ void sobel_kernel(const float* __restrict__ sob)
{
    __shared__ float ks[3 * 125];
    const int tid = threadIdx.x;
    for (int i = tid; i < 375; i += 256) ks[i] = sob[i];
    __syncthreads();
    int v = blockIdx.x * 256 + tid;
    if (v >= M3) return;
    int x = v & 127, y = (v >> 7) & 127, z = v >> 14;
    float a0 = 0.f, a1 = 0.f, a2 = 0.f;
    for (int kz = 0; kz < 5; kz++) { int zz = z + kz - 2; if ((unsigned)zz >= 128u) continue;
    for (int ky = 0; ky < 5; ky++) { int yy = y + ky - 2; if ((unsigned)yy >= 128u) continue;
    for (int kx = 0; kx < 5; kx++) { int xx = x + kx - 2; if ((unsigned)xx >= 128u) continue;
        float val = g_vols[(zz * 128 + yy) * 128 + xx];
        int k = kz * 25 + ky * 5 + kx;
        a0 += val * ks[k];
        a1 += val * ks[125 + k];
        a2 += val * ks[250 + k];
    }}}
    g_vols[16 * M3 + v] = a0;
    g_vols[17 * M3 + v] = a1;
    g_vols[18 * M3 + v] = a2;
}

// ------------- per-sample: ray AABB, trilinear gather, MLP -------------------
__global__ void __launch_bounds__(128)
sample_kernel(const float* __restrict__ rays_o, const float* __restrict__ rays_d,
              const float* __restrict__ viewdirs,
              const float* __restrict__ w0, const float* __restrict__ b0,
              const float* __restrict__ w1, const float* __restrict__ b1,
              const float* __restrict__ w2, const float* __restrict__ b2,
              const float* __restrict__ w3, const float* __restrict__ b3,
              float* __restrict__ out)
{
    __shared__ float s_w0[58 * 64];
    __shared__ float s_w1[64 * 64];
    __shared__ float s_w2[64 * 64];
    __shared__ float s_w3[64 * 3];
    const int tid = threadIdx.x;
    for (int i = tid; i < 58 * 64; i += 128) s_w0[i] = w0[i];
    for (int i = tid; i < 64 * 64; i += 128) { s_w1[i] = w1[i]; s_w2[i] = w2[i]; }
    for (int i = tid; i < 192; i += 128) s_w3[i] = w3[i];
    __syncthreads();

    int idx = blockIdx.x * 128 + tid;
    if (idx >= BRAYS * NSAMP) return;
    int ray = idx / NSAMP;
    int s   = idx - ray * NSAMP;

    float ox = rays_o[ray * 3 + 0], oy = rays_o[ray * 3 + 1], oz = rays_o[ray * 3 + 2];
    float dx = rays_d[ray * 3 + 0], dy = rays_d[ray * 3 + 1], dz = rays_d[ray * 3 + 2];
    float vx = (dx == 0.f) ? 1e-6f : dx;
    float vy = (dy == 0.f) ? 1e-6f : dy;
    float vz = (dz == 0.f) ? 1e-6f : dz;
    float rax = (1.f - ox) / vx, rbx = (-1.f - ox) / vx;
    float ray_ = (1.f - oy) / vy, rby = (-1.f - oy) / vy;
    float raz = (1.f - oz) / vz, rbz = (-1.f - oz) / vz;
    float tmn = fmaxf(fmaxf(fminf(rax, rbx), fminf(ray_, rby)), fminf(raz, rbz));
    float tmx = fminf(fminf(fmaxf(rax, rbx), fmaxf(ray_, rby)), fmaxf(raz, rbz));
    float t_min = fminf(fmaxf(tmn, 0.05f), 2.5f);
    float t_max = fminf(fmaxf(tmx, 0.05f), 2.5f);
    bool mask = (t_max <= t_min);
    float dn = sqrtf(dx * dx + dy * dy + dz * dz);
    float interpx = t_min + STEPV * (float)s / dn;
    float px = ox + dx * interpx, py = oy + dy * interpx, pz = oz + dz * interpx;
    mask = mask || (px < -1.f) || (px > 1.f) || (py < -1.f) || (py > 1.f)
                || (pz < -1.f) || (pz > 1.f);
    if (mask) {
        g_sdfs[idx] = 100.f;
        g_rgbs[idx * 3 + 0] = 0.f;
        g_rgbs[idx * 3 + 1] = 0.f;
        g_rgbs[idx * 3 + 2] = 0.f;
        if (s == NSAMP - 1) out[BRAYS * 5 + ray] = 0.f;
        return;
    }
    float fx = fminf(fmaxf((px + 1.f) * 63.5f, 0.f), 127.f);
    float fy = fminf(fmaxf((py + 1.f) * 63.5f, 0.f), 127.f);
    float fz = fminf(fmaxf((pz + 1.f) * 63.5f, 0.f), 127.f);
    int i0x = (int)floorf(fx), i0y = (int)floorf(fy), i0z = (int)floorf(fz);
    int i1x = min(i0x + 1, 127), i1y = min(i0y + 1, 127), i1z = min(i0z + 1, 127);
    float twx = fx - (float)i0x, twy = fy - (float)i0y, twz = fz - (float)i0z;
    float wx0 = 1.f - twx, wy0 = 1.f - twy, wz0 = 1.f - twz;
    int o00 = (i0x * 128 + i0y) * 128;
    int o01 = (i0x * 128 + i1y) * 128;
    int o10 = (i1x * 128 + i0y) * 128;
    int o11 = (i1x * 128 + i1y) * 128;
    float w000 = wx0 * wy0 * wz0, w001 = wx0 * wy0 * twz;
    float w010 = wx0 * twy * wz0, w011 = wx0 * twy * twz;
    float w100 = twx * wy0 * wz0, w101 = twx * wy0 * twz;
    float w110 = twx * twy * wz0, w111 = twx * twy * twz;
    float samp[19];
#pragma unroll
    for (int c = 0; c < 19; c++) {
        const float* vc = g_vols + c * M3;
        samp[c] = w000 * __ldg(&vc[o00 + i0z]) + w001 * __ldg(&vc[o00 + i1z])
                + w010 * __ldg(&vc[o01 + i0z]) + w011 * __ldg(&vc[o01 + i1z])
                + w100 * __ldg(&vc[o10 + i0z]) + w101 * __ldg(&vc[o10 + i1z])
                + w110 * __ldg(&vc[o11 + i0z]) + w111 * __ldg(&vc[o11 + i1z]);
    }
    g_sdfs[idx] = samp[0];
    float gx = samp[16], gy = samp[17], gz = samp[18];
    float gn = sqrtf(gx * gx + gy * gy + gz * gz);
    float inv = 1.f / fmaxf(gn, 1e-12f);
    float nxx = gx * inv, nyy = gy * inv, nzz = gz * inv;
    float ux = viewdirs[ray * 3 + 0], uy = viewdirs[ray * 3 + 1], uz = viewdirs[ray * 3 + 2];
    float dot = -(ux * nxx + uy * nyy + uz * nzz);
    if (s == NSAMP - 1) out[BRAYS * 5 + ray] = -dot;
    float rx = 2.f * dot * nxx + ux;
    float ry = 2.f * dot * nyy + uy;
    float rz = 2.f * dot * nzz + uz;

    // build input vector in (small, explicitly local) h[]; accumulators stay
    // register-resident because they're only ever indexed with constants.
    float h[58];
#pragma unroll
    for (int c = 0; c < 15; c++) h[c] = samp[1 + c];
    h[15] = dot;
    h[16] = rx; h[17] = ry; h[18] = rz;
    {
        int p = 19;
        float fr = 1.f;
#pragma unroll
        for (int e = 0; e < 6; e++) {
            float sx, cx, sy, cy, sz, cz;
            __sincosf(rx * fr, &sx, &cx);
            __sincosf(ry * fr, &sy, &cy);
            __sincosf(rz * fr, &sz, &cz);
            h[p + 0] = sx; h[p + 1] = sy; h[p + 2] = sz;
            h[p + 3] = cx; h[p + 4] = cy; h[p + 5] = cz;
            p += 6;
            fr *= 2.f;
        }
    }
    h[55] = px; h[56] = py; h[57] = pz;

    float acc[64];
#pragma unroll
    for (int j = 0; j < 64; j++) acc[j] = __ldg(&b0[j]);
#pragma unroll 1
    for (int i = 0; i < 58; i++) {
        float hv = h[i];
        const float4* wp = reinterpret_cast<const float4*>(s_w0 + i * 64);
#pragma unroll
        for (int j = 0; j < 16; j++) {
            float4 w4 = wp[j];
            acc[4*j+0] += hv * w4.x; acc[4*j+1] += hv * w4.y;
            acc[4*j+2] += hv * w4.z; acc[4*j+3] += hv * w4.w;
        }
    }
    float act[64];
#pragma unroll
    for (int j = 0; j < 64; j++) { act[j] = fmaxf(acc[j], 0.f); acc[j] = __ldg(&b1[j]); }
#pragma unroll 1
    for (int i = 0; i < 64; i++) {
        float hv = act[i];
        const float4* wp = reinterpret_cast<const float4*>(s_w1 + i * 64);
#pragma unroll
        for (int j = 0; j < 16; j++) {
            float4 w4 = wp[j];
            acc[4*j+0] += hv * w4.x; acc[4*j+1] += hv * w4.y;
            acc[4*j+2] += hv * w4.z; acc[4*j+3] += hv * w4.w;
        }
    }
#pragma unroll
    for (int j = 0; j < 64; j++) { act[j] = fmaxf(acc[j], 0.f); acc[j] = __ldg(&b2[j]); }
#pragma unroll 1
    for (int i = 0; i < 64; i++) {
        float hv = act[i];
        const float4* wp = reinterpret_cast<const float4*>(s_w2 + i * 64);
#pragma unroll
        for (int j = 0; j < 16; j++) {
            float4 w4 = wp[j];
            acc[4*j+0] += hv * w4.x; acc[4*j+1] += hv * w4.y;
            acc[4*j+2] += hv * w4.z; acc[4*j+3] += hv * w4.w;
        }
    }
#pragma unroll
    for (int j = 0; j < 64; j++) act[j] = fmaxf(acc[j], 0.f);
    float r0 = __ldg(&b3[0]), r1 = __ldg(&b3[1]), r2 = __ldg(&b3[2]);
#pragma unroll 1
    for (int i = 0; i < 64; i++) {
        float hv = act[i];
        r0 += hv * s_w3[i * 3 + 0];
        r1 += hv * s_w3[i * 3 + 1];
        r2 += hv * s_w3[i * 3 + 2];
    }
    g_rgbs[idx * 3 + 0] = r0;
    g_rgbs[idx * 3 + 1] = r1;
    g_rgbs[idx * 3 + 2] = r2;
}

// ---------------- per-ray compositing: warp-per-ray with product scan --------
__global__ void __launch_bounds__(256)
render_kernel(const float* __restrict__ rays_o,
              const float* __restrict__ rays_d,
              const float* __restrict__ variance,
              float* __restrict__ out)
{
    int warp = (blockIdx.x * 256 + threadIdx.x) >> 5;
    int lane = threadIdx.x & 31;
    if (warp >= BRAYS) return;
    int ray = warp;
    float scale = expf(variance[0] * 10.f);
    float ox = rays_o[ray * 3 + 0], oy = rays_o[ray * 3 + 1], oz = rays_o[ray * 3 + 2];
    float dx = rays_d[ray * 3 + 0], dy = rays_d[ray * 3 + 1], dz = rays_d[ray * 3 + 2];
    float vx = (dx == 0.f) ? 1e-6f : dx;
    float vy = (dy == 0.f) ? 1e-6f : dy;
    float vz = (dz == 0.f) ? 1e-6f : dz;
    float rax = (1.f - ox) / vx, rbx = (-1.f - ox) / vx;
    float ray_ = (1.f - oy) / vy, rby = (-1.f - oy) / vy;
    float raz = (1.f - oz) / vz, rbz = (-1.f - oz) / vz;
    float tmn = fmaxf(fmaxf(fminf(rax, rbx), fminf(ray_, rby)), fminf(raz, rbz));
    float t_min = fminf(fmaxf(tmn, 0.05f), 2.5f);
    float dn = sqrtf(dx * dx + dy * dy + dz * dz);
    float base_dist = t_min * dn;

    const float* sd = g_sdfs + ray * NSAMP;
    float T = 1.f, rgb0 = 0.f, rgb1 = 0.f, rgb2 = 0.f, depth = 0.f;

    for (int base = 0; base < NSAMP - 1; base += 32) {
        int s = base + lane;
        bool v = s < NSAMP - 1;
        float alpha = 0.f;
        if (v) {
            float s0 = 1.f / (1.f + expf(-sd[s] * scale));
            float s1 = 1.f / (1.f + expf(-sd[s + 1] * scale));
            alpha = fmaxf((s0 - s1) / (s0 + 1e-10f), 0.f);
        }
        float om = 1.f - alpha;
        float p = om;
#pragma unroll
        for (int off = 1; off < 32; off <<= 1) {
            float t = __shfl_up_sync(0xffffffffu, p, off);
            if (lane >= off) p *= t;
        }
        float excl = __shfl_up_sync(0xffffffffu, p, 1);
        if (lane == 0) excl = 1.f;
        float wgt = T * excl * alpha;
        if (v) {
            out[BRAYS * 6 + ray * (NSAMP - 1) + s] = wgt;
            rgb0 += wgt * g_rgbs[(ray * NSAMP + s) * 3 + 0];
            rgb1 += wgt * g_rgbs[(ray * NSAMP + s) * 3 + 1];
            rgb2 += wgt * g_rgbs[(ray * NSAMP + s) * 3 + 2];
            depth += wgt * (base_dist + STEPV * (float)s);
        }
        T *= __shfl_sync(0xffffffffu, p, 31);
    }
#pragma unroll
    for (int off = 16; off; off >>= 1) {
        rgb0 += __shfl_xor_sync(0xffffffffu, rgb0, off);
        rgb1 += __shfl_xor_sync(0xffffffffu, rgb1, off);
        rgb2 += __shfl_xor_sync(0xffffffffu, rgb2, off);
        depth += __shfl_xor_sync(0xffffffffu, depth, off);
    }
    if (lane == 0) {
        out[ray * 3 + 0] = rgb0;
        out[ray * 3 + 1] = rgb1;
        out[ray * 3 + 2] = rgb2;
        out[BRAYS * 3 + ray] = depth;
        out[BRAYS * 4 + ray] = T;
    }
}

// -----------------------------------------------------------------------------
extern "C" void kernel_launch(void* const* d_in, const int* in_sizes, int n_in,
                              void* d_out, int out_size)
{
    const float* rays_o   = (const float*)d_in[0];
    const float* rays_d   = (const float*)d_in[1];
    const float* viewdirs = (const float*)d_in[2];
    const float* grid     = (const float*)d_in[3];
    const float* c1_w     = (const float*)d_in[4];
    const float* c1_b     = (const float*)d_in[5];
    const float* bn1_g    = (const float*)d_in[6];
    const float* bn1_beta = (const float*)d_in[7];
    const float* bn1_m    = (const float*)d_in[8];
    const float* bn1_v    = (const float*)d_in[9];
    const float* c2_w     = (const float*)d_in[10];
    const float* c2_b     = (const float*)d_in[11];
    const float* bn2_g    = (const float*)d_in[12];
    const float* bn2_beta = (const float*)d_in[13];
    const float* bn2_m    = (const float*)d_in[14];
    const float* bn2_v    = (const float*)d_in[15];
    const float* c3_w     = (const float*)d_in[16];
    const float* c3_b     = (const float*)d_in[17];
    const float* sobel    = (const float*)d_in[18];
    const float* variance = (const float*)d_in[19];
    const float* w0       = (const float*)d_in[20];
    const float* b0       = (const float*)d_in[21];
    const float* w1       = (const float*)d_in[22];
    const float* b1       = (const float*)d_in[23];
    const float* w2       = (const float*)d_in[24];
    const float* b2       = (const float*)d_in[25];
    const float* w3       = (const float*)d_in[26];
    const float* b3       = (const float*)d_in[27];
    float* out = (float*)d_out;

    dim3 cgrid(8, 8, 16);
    conv3x3_kernel<12, 3, 1><<<cgrid, 256>>>(grid, c1_w, c1_b, bn1_g, bn1_beta, bn1_m, bn1_v);
    conv3x3_kernel<76, 19, 2><<<cgrid, 256>>>(grid, c2_w, c2_b, bn2_g, bn2_beta, bn2_m, bn2_v);
    deconv_kernel<<<dim3(8, 16, 16), 256>>>(grid, c3_w, c3_b);
    sobel_kernel<<<(M3 + 255) / 256, 256>>>(sobel);
    int total = BRAYS * NSAMP;
    sample_kernel<<<(total + 127) / 128, 128>>>(rays_o, rays_d, viewdirs,
                                                w0, b0, w1, b1, w2, b2, w3, b3, out);
    render_kernel<<<512, 256>>>(rays_o, rays_d, variance, out);
}

// round 3
// speedup vs baseline: 2.1229x; 1.1517x over previous
#include <cuda_runtime.h>
#include <math.h>

#define BRAYS 4096
#define NSAMP 447
#define N3 (64*64*64)          // 262144
#define M3 (128*128*128)       // 2097152
#define VCH 19
#define STEPV 0.015625f        // STEP * VOXEL

typedef unsigned long long u64;

__device__ __forceinline__ void fma2(u64& d, u64 a, u64 b) {
    asm("fma.rn.f32x2 %0, %1, %2, %0;" : "+l"(d) : "l"(a), "l"(b));
}
__device__ __forceinline__ u64 pack2(float lo, float hi) {
    u64 r;
    asm("mov.b64 %0, {%1, %2};" : "=l"(r) : "f"(lo), "f"(hi));
    return r;
}
__device__ __forceinline__ float2 unpack2(u64 v) {
    float2 r;
    asm("mov.b64 {%0, %1}, %2;" : "=f"(r.x), "=f"(r.y) : "l"(v));
    return r;
}

// ---------------- scratch (device globals; no runtime allocation) -----------
__device__ float g_x1[64 * N3];
__device__ float g_x2[64 * N3];
__device__ float g_vols[VCH * M3];
__device__ float g_sdfs[BRAYS * NSAMP];
__device__ float g_rgbs[BRAYS * NSAMP * 3];

// =================== tiled 3x3x3 conv + BN + ReLU ===========================
// out tile 8(x) x 8(y) x 4(z), 64 output channels. 256 threads:
// tid = cg(8 co-groups of 8) + 8*row(32 rows: ry 8 x rz 4). Thread owns
// 8 x-voxels x 8 output channels = 32 f32x2 accumulators (channel-paired).
template<int CIN, int NCH, int LAYER>
__global__ void __launch_bounds__(256) conv3x3_kernel(
    const float* __restrict__ src0,
    const float* __restrict__ w,
    const float* __restrict__ cb,
    const float* __restrict__ bg, const float* __restrict__ bb,
    const float* __restrict__ bm, const float* __restrict__ bv)
{
    __shared__ float s_in[4 * 6 * 10 * 12];   // [cil][z6][y10][x12]
    __shared__ float s_w[4 * 27 * 64];        // [cil][k27][co64]
    __shared__ float s_a[64], s_c[64];
    float* dst = (LAYER == 1) ? g_x1 : g_x2;

    const int tid = threadIdx.x;
    const int x0 = blockIdx.x * 8, y0 = blockIdx.y * 8, z0 = blockIdx.z * 4;
    if (tid < 64) {
        float s = bg[tid] * rsqrtf(bv[tid] + 1e-5f);
        s_a[tid] = s;
        s_c[tid] = cb[tid] * s + bb[tid] - bm[tid] * s;
    }
    const int cg = tid & 7;
    const int rowid = tid >> 3;
    const int ry = rowid & 7, rz = rowid >> 3;

    u64 acc2[8][4];   // [x][channel-pair]
#pragma unroll
    for (int x = 0; x < 8; x++)
#pragma unroll
        for (int c = 0; c < 4; c++) acc2[x][c] = 0ull;

    for (int ch = 0; ch < NCH; ch++) {
        __syncthreads();
        for (int i = tid; i < 4 * 720; i += 256) {
            int cil = i / 720, rem = i % 720;
            int z = rem / 120, y2 = (rem / 12) % 10, x = rem % 12;
            float vv = 0.f;
            int gx = x0 - 1 + x, gy = y0 - 1 + y2, gz = z0 - 1 + z;
            if (x < 10 && (unsigned)gx < 64u && (unsigned)gy < 64u && (unsigned)gz < 64u) {
                int ci = ch * 4 + cil;
                const float* sp = (ci < 12) ? (src0 + ci * N3) : (g_x1 + (ci - 12) * N3);
                vv = __ldg(&sp[(gz * 64 + gy) * 64 + gx]);
            }
            s_in[i] = vv;
        }
        for (int i = tid; i < 4 * 27 * 64; i += 256) {
            int co = i & 63, rest = i >> 6;
            int k = rest % 27, cil = rest / 27;
            s_w[i] = __ldg(&w[co * (CIN * 27) + (ch * 4 + cil) * 27 + k]);
        }
        __syncthreads();
#pragma unroll
        for (int cil = 0; cil < 4; cil++) {
            const float* inc = s_in + cil * 720;
            const float* wc  = s_w + cil * 27 * 64;
#pragma unroll
            for (int kz = 0; kz < 3; kz++)
#pragma unroll
            for (int ky = 0; ky < 3; ky++) {
                const float4* rp = (const float4*)(inc + ((rz + kz) * 10 + ry + ky) * 12);
                float4 ra = rp[0], rb = rp[1], rc = rp[2];
                float rr[10] = {ra.x, ra.y, ra.z, ra.w, rb.x, rb.y, rb.z, rb.w,
                                rc.x, rc.y};
                u64 rr2[10];
#pragma unroll
                for (int j = 0; j < 10; j++) rr2[j] = pack2(rr[j], rr[j]);
#pragma unroll
                for (int kx = 0; kx < 3; kx++) {
                    const u64* wp = (const u64*)(wc + (kz * 9 + ky * 3 + kx) * 64 + cg * 8);
                    u64 w2[4] = {wp[0], wp[1], wp[2], wp[3]};
#pragma unroll
                    for (int x = 0; x < 8; x++)
#pragma unroll
                        for (int c = 0; c < 4; c++)
                            fma2(acc2[x][c], rr2[kx + x], w2[c]);
                }
            }
        }
    }
    int vbase = ((z0 + rz) * 64 + (y0 + ry)) * 64 + x0;
#pragma unroll
    for (int cp = 0; cp < 4; cp++) {
        int co0 = cg * 8 + 2 * cp;
        float a0 = s_a[co0], c0 = s_c[co0];
        float a1 = s_a[co0 + 1], c1 = s_c[co0 + 1];
        float* dp0 = dst + co0 * N3 + vbase;
        float* dp1 = dp0 + N3;
#pragma unroll
        for (int x = 0; x < 8; x++) {
            float2 p = unpack2(acc2[x][cp]);
            dp0[x] = fmaxf(p.x * a0 + c0, 0.f);
            dp1[x] = fmaxf(p.y * a1 + c1, 0.f);
        }
    }
}

// ========= tiled transposed conv: 140 -> 16, k3, stride 2, 64^3 -> 128^3 ====
__global__ void __launch_bounds__(256) deconv_kernel(
    const float* __restrict__ src0,
    const float* __restrict__ w,
    const float* __restrict__ cb)
{
    __shared__ float s_in[4 * 5 * 5 * 10];  // [cil][z5][y5][x10]
    __shared__ float s_w[4 * 27 * 16];      // [cil][kz][ky][kx][co16], flipped

    const int tid = threadIdx.x;
    const int x0 = blockIdx.x * 16, y0 = blockIdx.y * 8, z0 = blockIdx.z * 8;
    const int qx = tid & 3, ty = (tid >> 2) & 7, tz = tid >> 5;
    const int oy = y0 + ty, oz = z0 + tz;

    int nzl, kzv[2], izv[2];
    if ((tz & 1) == 0) { nzl = 1; kzv[0] = 1; izv[0] = tz >> 1; kzv[1] = 1; izv[1] = tz >> 1; }
    else { nzl = 2; kzv[0] = 0; izv[0] = (tz - 1) >> 1; kzv[1] = 2; izv[1] = (tz + 1) >> 1; }
    int nyl, kyv[2], iyv[2];
    if ((ty & 1) == 0) { nyl = 1; kyv[0] = 1; iyv[0] = ty >> 1; kyv[1] = 1; iyv[1] = ty >> 1; }
    else { nyl = 2; kyv[0] = 0; iyv[0] = (ty - 1) >> 1; kyv[1] = 2; iyv[1] = (ty + 1) >> 1; }

    u64 acc2[4][8];   // [x][co-pair]
#pragma unroll
    for (int j = 0; j < 4; j++)
#pragma unroll
        for (int c = 0; c < 8; c++) acc2[j][c] = 0ull;

    const int bx2 = x0 >> 1, by2 = y0 >> 1, bz2 = z0 >> 1;

    for (int ch = 0; ch < 35; ch++) {
        __syncthreads();
        for (int i = tid; i < 4 * 250; i += 256) {
            int cil = i / 250, rem = i % 250;
            int z = rem / 50, y2 = (rem / 10) % 5, x = rem % 10;
            float vv = 0.f;
            int gx = bx2 + x, gy = by2 + y2, gz = bz2 + z;
            if (gx < 64 && gy < 64 && gz < 64) {
                int ci = ch * 4 + cil;
                const float* sp = (ci < 12) ? (src0 + ci * N3)
                                : (ci < 76) ? (g_x1 + (ci - 12) * N3)
                                            : (g_x2 + (ci - 76) * N3);
                vv = __ldg(&sp[(gz * 64 + gy) * 64 + gx]);
            }
            s_in[i] = vv;
        }
        for (int i = tid; i < 4 * 27 * 16; i += 256) {
            int co = i & 15, rest = i >> 4;
            int k = rest % 27, cil = rest / 27;
            int kz_ = k / 9, ky_ = (k / 3) % 3, kx_ = k % 3;
            s_w[i] = __ldg(&w[(ch * 4 + cil) * (16 * 27) + co * 27
                              + (2 - kz_) * 9 + (2 - ky_) * 3 + (2 - kx_)]);
        }
        __syncthreads();
#pragma unroll
        for (int cil = 0; cil < 4; cil++) {
            for (int a = 0; a < nzl; a++) {
                int kz = kzv[a], iz = izv[a];
                for (int b = 0; b < nyl; b++) {
                    int ky = kyv[b], iy = iyv[b];
                    const float* rowp = s_in + ((cil * 5 + iz) * 5 + iy) * 10 + 2 * qx;
                    float2 rA = *(const float2*)rowp;
                    float  r2v = rowp[2];
                    u64 r0p = pack2(rA.x, rA.x);
                    u64 r1p = pack2(rA.y, rA.y);
                    u64 r2p = pack2(r2v, r2v);
                    const float* wb = s_w + ((cil * 27) + kz * 9 + ky * 3) * 16;
                    const u64* q0 = (const u64*)wb;
                    const u64* q1 = (const u64*)(wb + 16);
                    const u64* q2 = (const u64*)(wb + 32);
#pragma unroll
                    for (int c = 0; c < 8; c++) {
                        u64 w0p = q0[c], w1p = q1[c], w2p = q2[c];
                        fma2(acc2[0][c], r0p, w1p);
                        fma2(acc2[1][c], r0p, w0p);
                        fma2(acc2[1][c], r1p, w2p);
                        fma2(acc2[2][c], r1p, w1p);
                        fma2(acc2[3][c], r1p, w0p);
                        fma2(acc2[3][c], r2p, w2p);
                    }
                }
            }
        }
    }
    int obase = (oz * 128 + oy) * 128 + x0 + 4 * qx;
#pragma unroll
    for (int c = 0; c < 8; c++) {
        float2 p0 = unpack2(acc2[0][c]);
        float2 p1 = unpack2(acc2[1][c]);
        float2 p2 = unpack2(acc2[2][c]);
        float2 p3 = unpack2(acc2[3][c]);
        int co0 = 2 * c;
        float b0v = __ldg(&cb[co0]), b1v = __ldg(&cb[co0 + 1]);
        *(float4*)(g_vols + co0 * M3 + obase) =
            make_float4(p0.x + b0v, p1.x + b0v, p2.x + b0v, p3.x + b0v);
        *(float4*)(g_vols + (co0 + 1) * M3 + obase) =
            make_float4(p0.y + b1v, p1.y + b1v, p2.y + b1v, p3.y + b1v);
    }
}

// ---------------- sobel: density -> 3 gradient channels, 5x5x5 pad2 ---------
__global__ void sobel_kernel(const float* __restrict__ sob)
{
    __shared__ float ks[3 * 125];
    const int tid = threadIdx.x;
    for (int i = tid; i < 375; i += 256) ks[i] = sob[i];
    __syncthreads();
    int v = blockIdx.x * 256 + tid;
    if (v >= M3) return;
    int x = v & 127, y = (v >> 7) & 127, z = v >> 14;
    float a0 = 0.f, a1 = 0.f, a2 = 0.f;
    for (int kz = 0; kz < 5; kz++) { int zz = z + kz - 2; if ((unsigned)zz >= 128u) continue;
    for (int ky = 0; ky < 5; ky++) { int yy = y + ky - 2; if ((unsigned)yy >= 128u) continue;
    for (int kx = 0; kx < 5; kx++) { int xx = x + kx - 2; if ((unsigned)xx >= 128u) continue;
        float val = g_vols[(zz * 128 + yy) * 128 + xx];
        int k = kz * 25 + ky * 5 + kx;
        a0 += val * ks[k];
        a1 += val * ks[125 + k];
        a2 += val * ks[250 + k];
    }}}
    g_vols[16 * M3 + v] = a0;
    g_vols[17 * M3 + v] = a1;
    g_vols[18 * M3 + v] = a2;
}

// ------------- per-sample: ray AABB, trilinear gather, MLP -------------------
__global__ void __launch_bounds__(128)
sample_kernel(const float* __restrict__ rays_o, const float* __restrict__ rays_d,
              const float* __restrict__ viewdirs,
              const float* __restrict__ w0, const float* __restrict__ b0,
              const float* __restrict__ w1, const float* __restrict__ b1,
              const float* __restrict__ w2, const float* __restrict__ b2,
              const float* __restrict__ w3, const float* __restrict__ b3,
              float* __restrict__ out)
{
    __shared__ float s_w0[58 * 64];
    __shared__ float s_w1[64 * 64];
    __shared__ float s_w2[64 * 64];
    __shared__ float s_w3[64 * 3];
    const int tid = threadIdx.x;
    for (int i = tid; i < 58 * 64; i += 128) s_w0[i] = w0[i];
    for (int i = tid; i < 64 * 64; i += 128) { s_w1[i] = w1[i]; s_w2[i] = w2[i]; }
    for (int i = tid; i < 192; i += 128) s_w3[i] = w3[i];
    __syncthreads();

    int idx = blockIdx.x * 128 + tid;
    if (idx >= BRAYS * NSAMP) return;
    int ray = idx / NSAMP;
    int s   = idx - ray * NSAMP;

    float ox = rays_o[ray * 3 + 0], oy = rays_o[ray * 3 + 1], oz = rays_o[ray * 3 + 2];
    float dx = rays_d[ray * 3 + 0], dy = rays_d[ray * 3 + 1], dz = rays_d[ray * 3 + 2];
    float vx = (dx == 0.f) ? 1e-6f : dx;
    float vy = (dy == 0.f) ? 1e-6f : dy;
    float vz = (dz == 0.f) ? 1e-6f : dz;
    float rax = (1.f - ox) / vx, rbx = (-1.f - ox) / vx;
    float ray_ = (1.f - oy) / vy, rby = (-1.f - oy) / vy;
    float raz = (1.f - oz) / vz, rbz = (-1.f - oz) / vz;
    float tmn = fmaxf(fmaxf(fminf(rax, rbx), fminf(ray_, rby)), fminf(raz, rbz));
    float tmx = fminf(fminf(fmaxf(rax, rbx), fmaxf(ray_, rby)), fmaxf(raz, rbz));
    float t_min = fminf(fmaxf(tmn, 0.05f), 2.5f);
    float t_max = fminf(fmaxf(tmx, 0.05f), 2.5f);
    bool mask = (t_max <= t_min);
    float dn = sqrtf(dx * dx + dy * dy + dz * dz);
    float interpx = t_min + STEPV * (float)s / dn;
    float px = ox + dx * interpx, py = oy + dy * interpx, pz = oz + dz * interpx;
    mask = mask || (px < -1.f) || (px > 1.f) || (py < -1.f) || (py > 1.f)
                || (pz < -1.f) || (pz > 1.f);
    if (mask) {
        g_sdfs[idx] = 100.f;
        g_rgbs[idx * 3 + 0] = 0.f;
        g_rgbs[idx * 3 + 1] = 0.f;
        g_rgbs[idx * 3 + 2] = 0.f;
        if (s == NSAMP - 1) out[BRAYS * 5 + ray] = 0.f;
        return;
    }
    float fx = fminf(fmaxf((px + 1.f) * 63.5f, 0.f), 127.f);
    float fy = fminf(fmaxf((py + 1.f) * 63.5f, 0.f), 127.f);
    float fz = fminf(fmaxf((pz + 1.f) * 63.5f, 0.f), 127.f);
    int i0x = (int)floorf(fx), i0y = (int)floorf(fy), i0z = (int)floorf(fz);
    int i1x = min(i0x + 1, 127), i1y = min(i0y + 1, 127), i1z = min(i0z + 1, 127);
    float twx = fx - (float)i0x, twy = fy - (float)i0y, twz = fz - (float)i0z;
    float wx0 = 1.f - twx, wy0 = 1.f - twy, wz0 = 1.f - twz;
    int o00 = (i0x * 128 + i0y) * 128;
    int o01 = (i0x * 128 + i1y) * 128;
    int o10 = (i1x * 128 + i0y) * 128;
    int o11 = (i1x * 128 + i1y) * 128;
    float w000 = wx0 * wy0 * wz0, w001 = wx0 * wy0 * twz;
    float w010 = wx0 * twy * wz0, w011 = wx0 * twy * twz;
    float w100 = twx * wy0 * wz0, w101 = twx * wy0 * twz;
    float w110 = twx * twy * wz0, w111 = twx * twy * twz;
    float samp[19];
#pragma unroll
    for (int c = 0; c < 19; c++) {
        const float* vc = g_vols + c * M3;
        samp[c] = w000 * __ldg(&vc[o00 + i0z]) + w001 * __ldg(&vc[o00 + i1z])
                + w010 * __ldg(&vc[o01 + i0z]) + w011 * __ldg(&vc[o01 + i1z])
                + w100 * __ldg(&vc[o10 + i0z]) + w101 * __ldg(&vc[o10 + i1z])
                + w110 * __ldg(&vc[o11 + i0z]) + w111 * __ldg(&vc[o11 + i1z]);
    }
    g_sdfs[idx] = samp[0];
    float gx = samp[16], gy = samp[17], gz = samp[18];
    float gn = sqrtf(gx * gx + gy * gy + gz * gz);
    float inv = 1.f / fmaxf(gn, 1e-12f);
    float nxx = gx * inv, nyy = gy * inv, nzz = gz * inv;
    float ux = viewdirs[ray * 3 + 0], uy = viewdirs[ray * 3 + 1], uz = viewdirs[ray * 3 + 2];
    float dot = -(ux * nxx + uy * nyy + uz * nzz);
    if (s == NSAMP - 1) out[BRAYS * 5 + ray] = -dot;
    float rx = 2.f * dot * nxx + ux;
    float ry = 2.f * dot * nyy + uy;
    float rz = 2.f * dot * nzz + uz;

    float h[58];
#pragma unroll
    for (int c = 0; c < 15; c++) h[c] = samp[1 + c];
    h[15] = dot;
    h[16] = rx; h[17] = ry; h[18] = rz;
    {
        int p = 19;
        float fr = 1.f;
#pragma unroll
        for (int e = 0; e < 6; e++) {
            float sx, cx, sy, cy, sz, cz;
            __sincosf(rx * fr, &sx, &cx);
            __sincosf(ry * fr, &sy, &cy);
            __sincosf(rz * fr, &sz, &cz);
            h[p + 0] = sx; h[p + 1] = sy; h[p + 2] = sz;
            h[p + 3] = cx; h[p + 4] = cy; h[p + 5] = cz;
            p += 6;
            fr *= 2.f;
        }
    }
    h[55] = px; h[56] = py; h[57] = pz;

    u64 acc2[32];
#pragma unroll
    for (int j = 0; j < 32; j++) {
        float2 bb = *(const float2*)(b0 + 2 * j);
        acc2[j] = pack2(bb.x, bb.y);
    }
#pragma unroll 1
    for (int i = 0; i < 58; i++) {
        u64 hv2 = pack2(h[i], h[i]);
        const u64* wp = (const u64*)(s_w0 + i * 64);
#pragma unroll
        for (int j = 0; j < 32; j++) fma2(acc2[j], hv2, wp[j]);
    }
    float act[64];
#pragma unroll
    for (int j = 0; j < 32; j++) {
        float2 p = unpack2(acc2[j]);
        act[2*j] = fmaxf(p.x, 0.f); act[2*j+1] = fmaxf(p.y, 0.f);
        float2 bb = *(const float2*)(b1 + 2 * j);
        acc2[j] = pack2(bb.x, bb.y);
    }
#pragma unroll 1
    for (int i = 0; i < 64; i++) {
        u64 hv2 = pack2(act[i], act[i]);
        const u64* wp = (const u64*)(s_w1 + i * 64);
#pragma unroll
        for (int j = 0; j < 32; j++) fma2(acc2[j], hv2, wp[j]);
    }
#pragma unroll
    for (int j = 0; j < 32; j++) {
        float2 p = unpack2(acc2[j]);
        act[2*j] = fmaxf(p.x, 0.f); act[2*j+1] = fmaxf(p.y, 0.f);
        float2 bb = *(const float2*)(b2 + 2 * j);
        acc2[j] = pack2(bb.x, bb.y);
    }
#pragma unroll 1
    for (int i = 0; i < 64; i++) {
        u64 hv2 = pack2(act[i], act[i]);
        const u64* wp = (const u64*)(s_w2 + i * 64);
#pragma unroll
        for (int j = 0; j < 32; j++) fma2(acc2[j], hv2, wp[j]);
    }
#pragma unroll
    for (int j = 0; j < 32; j++) {
        float2 p = unpack2(acc2[j]);
        act[2*j] = fmaxf(p.x, 0.f); act[2*j+1] = fmaxf(p.y, 0.f);
    }
    float r0 = __ldg(&b3[0]), r1 = __ldg(&b3[1]), r2 = __ldg(&b3[2]);
#pragma unroll 1
    for (int i = 0; i < 64; i++) {
        float hv = act[i];
        r0 += hv * s_w3[i * 3 + 0];
        r1 += hv * s_w3[i * 3 + 1];
        r2 += hv * s_w3[i * 3 + 2];
    }
    g_rgbs[idx * 3 + 0] = r0;
    g_rgbs[idx * 3 + 1] = r1;
    g_rgbs[idx * 3 + 2] = r2;
}

// ---------------- per-ray compositing: warp-per-ray with product scan --------
__global__ void __launch_bounds__(256)
render_kernel(const float* __restrict__ rays_o,
              const float* __restrict__ rays_d,
              const float* __restrict__ variance,
              float* __restrict__ out)
{
    int warp = (blockIdx.x * 256 + threadIdx.x) >> 5;
    int lane = threadIdx.x & 31;
    if (warp >= BRAYS) return;
    int ray = warp;
    float scale = expf(variance[0] * 10.f);
    float ox = rays_o[ray * 3 + 0], oy = rays_o[ray * 3 + 1], oz = rays_o[ray * 3 + 2];
    float dx = rays_d[ray * 3 + 0], dy = rays_d[ray * 3 + 1], dz = rays_d[ray * 3 + 2];
    float vx = (dx == 0.f) ? 1e-6f : dx;
    float vy = (dy == 0.f) ? 1e-6f : dy;
    float vz = (dz == 0.f) ? 1e-6f : dz;
    float rax = (1.f - ox) / vx, rbx = (-1.f - ox) / vx;
    float ray_ = (1.f - oy) / vy, rby = (-1.f - oy) / vy;
    float raz = (1.f - oz) / vz, rbz = (-1.f - oz) / vz;
    float tmn = fmaxf(fmaxf(fminf(rax, rbx), fminf(ray_, rby)), fminf(raz, rbz));
    float t_min = fminf(fmaxf(tmn, 0.05f), 2.5f);
    float dn = sqrtf(dx * dx + dy * dy + dz * dz);
    float base_dist = t_min * dn;

    const float* sd = g_sdfs + ray * NSAMP;
    float T = 1.f, rgb0 = 0.f, rgb1 = 0.f, rgb2 = 0.f, depth = 0.f;

    for (int base = 0; base < NSAMP - 1; base += 32) {
        int s = base + lane;
        bool v = s < NSAMP - 1;
        float alpha = 0.f;
        if (v) {
            float s0 = 1.f / (1.f + expf(-sd[s] * scale));
            float s1 = 1.f / (1.f + expf(-sd[s + 1] * scale));
            alpha = fmaxf((s0 - s1) / (s0 + 1e-10f), 0.f);
        }
        float om = 1.f - alpha;
        float p = om;
#pragma unroll
        for (int off = 1; off < 32; off <<= 1) {
            float t = __shfl_up_sync(0xffffffffu, p, off);
            if (lane >= off) p *= t;
        }
        float excl = __shfl_up_sync(0xffffffffu, p, 1);
        if (lane == 0) excl = 1.f;
        float wgt = T * excl * alpha;
        if (v) {
            out[BRAYS * 6 + ray * (NSAMP - 1) + s] = wgt;
            rgb0 += wgt * g_rgbs[(ray * NSAMP + s) * 3 + 0];
            rgb1 += wgt * g_rgbs[(ray * NSAMP + s) * 3 + 1];
            rgb2 += wgt * g_rgbs[(ray * NSAMP + s) * 3 + 2];
            depth += wgt * (base_dist + STEPV * (float)s);
        }
        T *= __shfl_sync(0xffffffffu, p, 31);
    }
#pragma unroll
    for (int off = 16; off; off >>= 1) {
        rgb0 += __shfl_xor_sync(0xffffffffu, rgb0, off);
        rgb1 += __shfl_xor_sync(0xffffffffu, rgb1, off);
        rgb2 += __shfl_xor_sync(0xffffffffu, rgb2, off);
        depth += __shfl_xor_sync(0xffffffffu, depth, off);
    }
    if (lane == 0) {
        out[ray * 3 + 0] = rgb0;
        out[ray * 3 + 1] = rgb1;
        out[ray * 3 + 2] = rgb2;
        out[BRAYS * 3 + ray] = depth;
        out[BRAYS * 4 + ray] = T;
    }
}

// -----------------------------------------------------------------------------
extern "C" void kernel_launch(void* const* d_in, const int* in_sizes, int n_in,
                              void* d_out, int out_size)
{
    const float* rays_o   = (const float*)d_in[0];
    const float* rays_d   = (const float*)d_in[1];
    const float* viewdirs = (const float*)d_in[2];
    const float* grid     = (const float*)d_in[3];
    const float* c1_w     = (const float*)d_in[4];
    const float* c1_b     = (const float*)d_in[5];
    const float* bn1_g    = (const float*)d_in[6];
    const float* bn1_beta = (const float*)d_in[7];
    const float* bn1_m    = (const float*)d_in[8];
    const float* bn1_v    = (const float*)d_in[9];
    const float* c2_w     = (const float*)d_in[10];
    const float* c2_b     = (const float*)d_in[11];
    const float* bn2_g    = (const float*)d_in[12];
    const float* bn2_beta = (const float*)d_in[13];
    const float* bn2_m    = (const float*)d_in[14];
    const float* bn2_v    = (const float*)d_in[15];
    const float* c3_w     = (const float*)d_in[16];
    const float* c3_b     = (const float*)d_in[17];
    const float* sobel    = (const float*)d_in[18];
    const float* variance = (const float*)d_in[19];
    const float* w0       = (const float*)d_in[20];
    const float* b0       = (const float*)d_in[21];
    const float* w1       = (const float*)d_in[22];
    const float* b1       = (const float*)d_in[23];
    const float* w2       = (const float*)d_in[24];
    const float* b2       = (const float*)d_in[25];
    const float* w3       = (const float*)d_in[26];
    const float* b3       = (const float*)d_in[27];
    float* out = (float*)d_out;

    dim3 cgrid(8, 8, 16);
    conv3x3_kernel<12, 3, 1><<<cgrid, 256>>>(grid, c1_w, c1_b, bn1_g, bn1_beta, bn1_m, bn1_v);
    conv3x3_kernel<76, 19, 2><<<cgrid, 256>>>(grid, c2_w, c2_b, bn2_g, bn2_beta, bn2_m, bn2_v);
    deconv_kernel<<<dim3(8, 16, 16), 256>>>(grid, c3_w, c3_b);
    sobel_kernel<<<(M3 + 255) / 256, 256>>>(sobel);
    int total = BRAYS * NSAMP;
    sample_kernel<<<(total + 127) / 128, 128>>>(rays_o, rays_d, viewdirs,
                                                w0, b0, w1, b1, w2, b2, w3, b3, out);
    render_kernel<<<512, 256>>>(rays_o, rays_d, variance, out);
}